// round 9
// baseline (speedup 1.0000x reference)
#include <cuda_runtime.h>

// ---------------- problem constants ----------------
#define NN     12288
#define INFEAT 128
#define OF     64
#define AL     0.2f

// ---------------- main-kernel tiling ----------------
#define JSPLIT 3
#define JSL    (NN / JSPLIT)     /* 4096 columns per block */
#define TJ     32                /* j-tile */
#define NTILE  (JSL / TJ)        /* 128 tiles */
#define RB     128               /* rows per block */
#define NRB    (NN / RB)         /* 96 row-blocks */
#define RP     138               /* Psm row pad: 8B-align planes, 2-phase STS */
#define PSTR   68                /* partial stride: 64 feats + den + pad */

// ---------------- device scratch (static globals: allowed) ----------------
__device__ __align__(16) float  g_h[NN * OF];                        // 3 MB
__device__ float  g_c[NN];
__device__ float  g_d[NN];
__device__ __align__(16) float4 g_rowc[NN];    // (-c_i, A_i, A'_i, 0)
__device__ __align__(16) float4 g_scalJ[NN];   // (d_j, B_j, B'_j, 0)
__device__ __align__(16) float  g_part[(size_t)JSPLIT * NN * PSTR];  // 10 MB
__device__ unsigned g_dmax_enc;

// monotone float<->unsigned encode for atomicMax over signed floats
__device__ __forceinline__ unsigned fenc(float f) {
    unsigned b = __float_as_uint(f);
    return (b & 0x80000000u) ? ~b : (b | 0x80000000u);
}
__device__ __forceinline__ float fdec(unsigned u) {
    return (u & 0x80000000u) ? __uint_as_float(u & 0x7fffffffu)
                             : __uint_as_float(~u);
}

__device__ __forceinline__ unsigned su(const void* p) {
    unsigned r;
    asm("{ .reg .u64 t; cvta.to.shared.u64 t, %1; cvt.u32.u64 %0, t; }"
        : "=r"(r) : "l"(p));
    return r;
}

#define FMA2(acc_, a_, b_) \
    asm("fma.rn.f32x2 %0, %1, %2, %0;" : "+l"(acc_) : "l"(a_), "l"(b_))

// ---------------- K0: reset dmax atomic (replay-safe) ----------------
__global__ void k_reset() { g_dmax_enc = 0u; }

// ---------------- K1: h = input @ W  (16 rows/block, 256 thr) --------
__global__ void __launch_bounds__(256) k_linear(const float* __restrict__ x,
                                                const float* __restrict__ W) {
    __shared__ __align__(16) float Wsm[INFEAT * OF];  // 32 KB
    __shared__ __align__(16) float Xsm[16 * INFEAT];  // 8 KB
    int tid = threadIdx.x;
    int i0  = blockIdx.x * 16;

    const float4* Wg  = (const float4*)W;
    float4*       Ws4 = (float4*)Wsm;
    #pragma unroll
    for (int e = tid; e < INFEAT * OF / 4; e += 256) Ws4[e] = Wg[e];

    const float4* Xg  = (const float4*)(x + (size_t)i0 * INFEAT);
    float4*       Xs4 = (float4*)Xsm;
    #pragma unroll
    for (int e = tid; e < 16 * INFEAT / 4; e += 256) Xs4[e] = Xg[e];
    __syncthreads();

    int f  = tid & 63;
    int rt = tid >> 6;  // 0..3 -> 4 rows each
    float acc[4] = {0.f, 0.f, 0.f, 0.f};
    #pragma unroll 4
    for (int k = 0; k < INFEAT; k++) {
        float w = Wsm[k * OF + f];
        #pragma unroll
        for (int j = 0; j < 4; j++)
            acc[j] += Xsm[(rt * 4 + j) * INFEAT + k] * w;
    }
    #pragma unroll
    for (int j = 0; j < 4; j++)
        g_h[(size_t)(i0 + rt * 4 + j) * OF + f] = acc[j];
}

// ---------------- K2: c_i = h_i.a1, d_i = h_i.a2, global dmax --------
__global__ void __launch_bounds__(256) k_attvec(const float* __restrict__ a) {
    __shared__ float sred[8];
    int tid  = threadIdx.x;
    int lane = tid & 31, wid = tid >> 5;
    int i = blockIdx.x * 8 + wid;
    float h0 = g_h[(size_t)i * OF + lane];
    float h1 = g_h[(size_t)i * OF + 32 + lane];
    float c = h0 * __ldg(a + lane)      + h1 * __ldg(a + 32 + lane);
    float d = h0 * __ldg(a + 64 + lane) + h1 * __ldg(a + 96 + lane);
    #pragma unroll
    for (int s = 16; s; s >>= 1) {
        c += __shfl_xor_sync(0xffffffffu, c, s);
        d += __shfl_xor_sync(0xffffffffu, d, s);
    }
    if (lane == 0) { g_c[i] = c; g_d[i] = d; sred[wid] = d; }
    __syncthreads();
    if (tid == 0) {
        float m = sred[0];
        #pragma unroll
        for (int w = 1; w < 8; w++) m = fmaxf(m, sred[w]);
        atomicMax(&g_dmax_enc, fenc(m));
    }
}

// ---------------- K3: per-row / per-col softmax factors --------------
__global__ void __launch_bounds__(256) k_factors() {
    int i = blockIdx.x * 256 + threadIdx.x;
    float dmax = fdec(g_dmax_enc);
    float c = g_c[i], d = g_d[i];
    float cm = c + dmax;
    float s = cm > 0.f ? cm : AL * cm;          // s_i = lrelu(c_i + dmax)
    g_rowc[i]  = make_float4(-c, expf(cm - s), expf(AL * cm - s), 0.f);
    float dm = d - dmax;
    g_scalJ[i] = make_float4(d, expf(dm), expf(AL * dm), 0.f);
}

// ---------------- K4: main fused masked-softmax-weighted aggregation --
// block (rb, js): rows rb*128..+127, cols js*4096..+4095
// phase1: adj -> p -> Psm[j][row] (transposed) + den
// phase2: acc[rowpair][feat] += {p_r,p_r+1} * {h_f,h_f}  via fma.rn.f32x2
__global__ void __launch_bounds__(128) k_main(const int* __restrict__ adj) {
    __shared__ __align__(16) float Psm[TJ * RP];      // 17664 B
    __shared__ __align__(16) float Hd[TJ * OF * 2];   // duplicated h: 16 KB
    __shared__ float Den[RB];

    int tid = threadIdx.x;
    int rowbase = blockIdx.x * RB;
    int js = blockIdx.y;
    int jbase = js * JSL;

    // phase-1 ids
    int s  = tid & 7;        // 8 j-segments of 4 (one int4)
    int rr = tid >> 3;       // 0..15 -> row within pass
    // phase-2 ids
    int fg = tid & 7;        // feat group (8 feats)
    int rg = tid >> 3;       // row group (8 rows), 0..15

    unsigned psmU = su(Psm), hdU = su(Hd);
    unsigned pBase0 = psmU + (unsigned)(rg * 8 * 4);  // + jl*RP*4
    unsigned hBase0 = hdU + (unsigned)(fg * 64);      // + jl*512

    unsigned long long acc[32];
    #pragma unroll
    for (int i = 0; i < 32; i++) acc[i] = 0ull;
    if (tid < RB) Den[tid] = 0.f;

    for (int T = 0; T < NTILE; T++) {
        int j0 = jbase + T * TJ;
        __syncthreads();  // previous tile's phase-2 done with smem

        // ---- fill Hd (dup): thread: jl = tid>>2, q = tid&3 (16 feats)
        {
            int jl = tid >> 2, q = tid & 3;
            const float4* hp = (const float4*)(g_h + (size_t)(j0 + jl) * OF) + q * 4;
            float4* dp = ((float4*)Hd) + jl * (OF / 2) + q * 8;
            #pragma unroll
            for (int u = 0; u < 4; u++) {
                float4 v = hp[u];
                dp[2 * u]     = make_float4(v.x, v.x, v.y, v.y);
                dp[2 * u + 1] = make_float4(v.z, v.z, v.w, v.w);
            }
        }

        // ---- per-thread column factors (global, L1/L2 hot)
        float4 sc[4];
        #pragma unroll
        for (int e = 0; e < 4; e++) sc[e] = __ldg(g_scalJ + j0 + s * 4 + e);

        // ---- adj prefetch (8 int4 = 32 cols x 8 passes of 16 rows)
        const int4* ap = (const int4*)(adj + (size_t)rowbase * NN + j0) + s;
        int4 av[8];
        #pragma unroll
        for (int p = 0; p < 8; p++)
            av[p] = ap[(size_t)(p * 16 + rr) * (NN / 4)];

        // ---- compute P tile + den
        #pragma unroll
        for (int p = 0; p < 8; p++) {
            int row = p * 16 + rr;
            float4 rc = __ldg(g_rowc + rowbase + row);
            int a4[4] = {av[p].x, av[p].y, av[p].z, av[p].w};
            float psum = 0.f;
            float pv[4];
            #pragma unroll
            for (int e = 0; e < 4; e++) {
                float4 s4 = sc[e];
                bool  pos = s4.x > rc.x;                  // d_j > -c_i
                float fa  = pos ? rc.y : rc.z;
                float fb  = pos ? s4.y : s4.z;
                float pp  = (a4[e] != 0) ? fa * fb : 0.f;
                pv[e] = pp;
                psum += pp;
            }
            #pragma unroll
            for (int e = 0; e < 4; e++)
                Psm[(s * 4 + e) * RP + row] = pv[e];
            psum += __shfl_down_sync(0xffffffffu, psum, 4, 8);
            psum += __shfl_down_sync(0xffffffffu, psum, 2, 8);
            psum += __shfl_down_sync(0xffffffffu, psum, 1, 8);
            if (s == 0) Den[row] += psum;   // unique owner per row, no race
        }
        __syncthreads();

        // ---- phase 2: register GEMM over 32 j's
        unsigned pA = pBase0, hA = hBase0;
        #pragma unroll 2
        for (int jl = 0; jl < TJ; jl++) {
            unsigned long long p0, p1, p2, p3, hh[8];
            asm volatile("ld.shared.b64 %0,[%1];" : "=l"(p0) : "r"(pA));
            asm volatile("ld.shared.b64 %0,[%1];" : "=l"(p1) : "r"(pA + 8));
            asm volatile("ld.shared.b64 %0,[%1];" : "=l"(p2) : "r"(pA + 16));
            asm volatile("ld.shared.b64 %0,[%1];" : "=l"(p3) : "r"(pA + 24));
            asm volatile("ld.shared.v2.b64 {%0,%1},[%2];" : "=l"(hh[0]), "=l"(hh[1]) : "r"(hA));
            asm volatile("ld.shared.v2.b64 {%0,%1},[%2];" : "=l"(hh[2]), "=l"(hh[3]) : "r"(hA + 16));
            asm volatile("ld.shared.v2.b64 {%0,%1},[%2];" : "=l"(hh[4]), "=l"(hh[5]) : "r"(hA + 32));
            asm volatile("ld.shared.v2.b64 {%0,%1},[%2];" : "=l"(hh[6]), "=l"(hh[7]) : "r"(hA + 48));
            #pragma unroll
            for (int t = 0; t < 8; t++) {
                FMA2(acc[t],      p0, hh[t]);
                FMA2(acc[8 + t],  p1, hh[t]);
                FMA2(acc[16 + t], p2, hh[t]);
                FMA2(acc[24 + t], p3, hh[t]);
            }
            pA += RP * 4;
            hA += 512;
        }
    }

    // ---- write partials (no atomics, unique writer per element)
    float* part = g_part + (size_t)js * NN * PSTR;
    #pragma unroll
    for (int k = 0; k < 4; k++) {
        int r0 = rowbase + rg * 8 + 2 * k;
        #pragma unroll
        for (int t = 0; t < 8; t++) {
            float lo, hi;
            asm("mov.b64 {%0,%1}, %2;" : "=f"(lo), "=f"(hi) : "l"(acc[k * 8 + t]));
            part[(size_t)r0 * PSTR + fg * 8 + t]       = lo;
            part[(size_t)(r0 + 1) * PSTR + fg * 8 + t] = hi;
        }
    }
    if (tid < RB)
        part[(size_t)(rowbase + tid) * PSTR + OF] = Den[tid];
}

// ---------------- K5: reduce partials, divide, elu -------------------
__global__ void __launch_bounds__(256) k_out(float* __restrict__ out) {
    int idx = blockIdx.x * 256 + threadIdx.x;   // < NN*OF
    int row = idx >> 6, f = idx & 63;
    size_t base = (size_t)row * PSTR;
    float num = 0.f, den = 0.f;
    #pragma unroll
    for (int js = 0; js < JSPLIT; js++) {
        const float* p = g_part + (size_t)js * NN * PSTR + base;
        num += p[f];
        den += p[OF];
    }
    float v = num / den;
    out[idx] = v > 0.f ? v : expm1f(v);
}

// ---------------- launch ----------------
extern "C" void kernel_launch(void* const* d_in, const int* in_sizes, int n_in,
                              void* d_out, int out_size) {
    (void)out_size;
    const float* input = nullptr;
    const int*   adj   = nullptr;
    const float* W     = nullptr;
    const float* a     = nullptr;
    for (int i = 0; i < n_in; i++) {
        switch (in_sizes[i]) {
            case NN * INFEAT:        input = (const float*)d_in[i]; break;
            case INFEAT * OF:        W     = (const float*)d_in[i]; break;
            case 2 * OF:             a     = (const float*)d_in[i]; break;
            default:
                if ((long long)in_sizes[i] == (long long)NN * NN)
                    adj = (const int*)d_in[i];
                break;
        }
    }
    if (!input) input = (const float*)d_in[0];
    if (!adj)   adj   = (const int*)d_in[1];
    if (!W)     W     = (const float*)d_in[2];
    if (!a)     a     = (const float*)d_in[3];

    k_reset<<<1, 1>>>();
    k_linear<<<NN / 16, 256>>>(input, W);
    k_attvec<<<NN / 8, 256>>>(a);
    k_factors<<<NN / 256, 256>>>();
    k_main<<<dim3(NRB, JSPLIT), 128>>>(adj);
    k_out<<<NN * OF / 256, 256>>>((float*)d_out);
}